// round 4
// baseline (speedup 1.0000x reference)
#include <cuda_runtime.h>
#include <math.h>

#define H        128
#define STRIDE   132      // 132 % 32 == 4 -> conflict-free row AND column smem access
#define VS       136      // vector stride between samples (8 mod 32 -> store-conflict-free)
#define NCTA     128
#define NTHREADS 512
#define MAXIT    500
#define LAG      4
#define TOLF     1e-3f

__device__ float g_res[MAXIT];   // per-iteration residual accumulators
__device__ int   g_cnt[MAXIT];   // per-iteration post counters (safe under skew)

struct __align__(16) Smem {
    float Wy0[H * STRIDE];
    float Wy1[H * STRIDE];
    float W1p[H * STRIDE];
    float yv0[2 * VS];
    float yv1[2 * VS];
    float zz [2 * VS];
    float v2 [2 * VS];
    float v1 [2 * VS];
    float xbuf[2 * VS];
    float ubuf[2 * VS];
    float redW[16][2];
    int   flag;
};

__global__ void pblnn_init_kernel() {
    int t = blockIdx.x * blockDim.x + threadIdx.x;
    if (t < MAXIT) { g_res[t] = 0.f; g_cnt[t] = 0; }
}

__device__ __forceinline__ float softplus_f(float s) {
    float e = __expf(s);
    float z = __logf(1.f + e);
    return (s > 15.f) ? s : z;
}

__device__ __forceinline__ void spsig(float s, float& z, float& sg) {
    float e = __expf(s);
    float zz_ = __logf(1.f + e);
    float sgg = e / (1.f + e);
    if (s > 15.f) { zz_ = s; sgg = 1.f; }
    z = zz_; sg = sgg;
}

// quarter-split dual-sample dot against a gmem row; butterfly-reduced over q.
// v0/v1: smem vectors (full 128); w: gmem row; k0 = 32*q.
__device__ __forceinline__ float2 dotq(const float* v0, const float* v1,
                                       const float* __restrict__ w, int k0) {
    float a0 = 0.f, a1 = 0.f;
#pragma unroll
    for (int c = 0; c < 8; c++) {
        float4 wv = __ldg((const float4*)&w[k0 + 4 * c]);
        float4 x0 = *(const float4*)&v0[k0 + 4 * c];
        float4 x1 = *(const float4*)&v1[k0 + 4 * c];
        a0 += wv.x * x0.x + wv.y * x0.y + wv.z * x0.z + wv.w * x0.w;
        a1 += wv.x * x1.x + wv.y * x1.y + wv.z * x1.z + wv.w * x1.w;
    }
    a0 += __shfl_xor_sync(0xffffffffu, a0, 1);
    a0 += __shfl_xor_sync(0xffffffffu, a0, 2);
    a1 += __shfl_xor_sync(0xffffffffu, a1, 1);
    a1 += __shfl_xor_sync(0xffffffffu, a1, 2);
    return make_float2(a0, a1);
}

__global__ __launch_bounds__(NTHREADS, 1)
void pblnn_kernel(
    const float* __restrict__ x,      const float* __restrict__ y,
    const float* __restrict__ wuu0_w, const float* __restrict__ wuu0_b,
    const float* __restrict__ wyu0_w, const float* __restrict__ wyu0_b,
    const float* __restrict__ wy0,
    const float* __restrict__ wu0_w,  const float* __restrict__ wu0_b,
    const float* __restrict__ wuu1_w, const float* __restrict__ wuu1_b,
    const float* __restrict__ wzu1_w, const float* __restrict__ wzu1_b,
    const float* __restrict__ wz1,
    const float* __restrict__ wyu1_w, const float* __restrict__ wyu1_b,
    const float* __restrict__ wy1,
    const float* __restrict__ wu1_w,  const float* __restrict__ wu1_b,
    const float* __restrict__ wzu2_w, const float* __restrict__ wzu2_b,
    const float* __restrict__ wz2,
    const float* __restrict__ wyu2_w, const float* __restrict__ wyu2_b,
    const float* __restrict__ wy2,
    float* __restrict__ out)
{
    extern __shared__ char smem_raw[];
    Smem& S = *reinterpret_cast<Smem*>(smem_raw);

    const int tid  = threadIdx.x;
    const int lane = tid & 31;
    const int wrp  = tid >> 5;
    const int h    = tid >> 2;          // 0..127
    const int q    = tid & 3;           // quarter
    const int k0   = q * 32;
    const bool act = (q < 2);           // elementwise lanes; s = q
    const int s    = q;                 // only meaningful when act
    const int samp = blockIdx.x * 2;

    // ---- stage x + weights into smem ----
    for (int e = tid; e < 2 * H; e += NTHREADS)
        S.xbuf[(e >> 7) * VS + (e & 127)] = x[samp * H + e];
    for (int e = tid; e < H * H / 4; e += NTHREADS) {
        int r = e >> 5, c4 = (e & 31) * 4;
        *(float4*)&S.Wy0[r * STRIDE + c4] = __ldg((const float4*)&wy0[r * H + c4]);
        *(float4*)&S.Wy1[r * STRIDE + c4] = __ldg((const float4*)&wy1[r * H + c4]);
        float4 wv = __ldg((const float4*)&wz1[r * H + c4]);
        wv.x = fmaxf(wv.x, 0.f); wv.y = fmaxf(wv.y, 0.f);
        wv.z = fmaxf(wv.z, 0.f); wv.w = fmaxf(wv.w, 0.f);
        *(float4*)&S.W1p[r * STRIDE + c4] = wv;
    }
    __syncthreads();

    // ---- y-independent precompute (split over q, butterfly-reduced) ----
    float a0r = 0.f, a1r = 0.f, c0r = 0.f, c1r = 0.f, zur = 0.f;
    float vw2 = 0.f, a2w = 0.f, yr = 0.f;
    float y1r = 1.f, y1h1 = 1.f, y1h2 = 1.f, y1h3 = 1.f, y1h4 = 1.f;
    float zs1r = 0.f, gAr = 0.f;

    {
        float2 duu = dotq(&S.xbuf[0], &S.xbuf[VS], &wuu0_w[h * H], k0);
        float2 da0 = dotq(&S.xbuf[0], &S.xbuf[VS], &wyu0_w[h * H], k0);
        float2 dc0 = dotq(&S.xbuf[0], &S.xbuf[VS], &wu0_w[h * H], k0);
        if (act) {
            float u0 = softplus_f(((s == 0) ? duu.x : duu.y) + wuu0_b[h]);
            a0r = ((s == 0) ? da0.x : da0.y) + wyu0_b[h];
            c0r = ((s == 0) ? dc0.x : dc0.y) + wu0_b[h];
            S.ubuf[s * VS + h] = u0;
        }
    }
    __syncthreads();
    float u1v = 0.f;
    {
        float2 du1 = dotq(&S.ubuf[0], &S.ubuf[VS], &wuu1_w[h * H], k0);
        float2 dzu = dotq(&S.ubuf[0], &S.ubuf[VS], &wzu1_w[h * H], k0);
        float2 da1 = dotq(&S.ubuf[0], &S.ubuf[VS], &wyu1_w[h * H], k0);
        float2 dc1 = dotq(&S.ubuf[0], &S.ubuf[VS], &wu1_w[h * H], k0);
        if (act) {
            u1v = softplus_f(((s == 0) ? du1.x : du1.y) + wuu1_b[h]);
            zur = softplus_f(((s == 0) ? dzu.x : dzu.y) + wzu1_b[h]);
            a1r = ((s == 0) ? da1.x : da1.y) + wyu1_b[h];
            c1r = ((s == 0) ? dc1.x : dc1.y) + wu1_b[h];
        }
    }
    __syncthreads();
    if (act) S.ubuf[s * VS + h] = u1v;
    __syncthreads();
    {
        float2 da2 = dotq(&S.ubuf[0], &S.ubuf[VS], &wyu2_w[h * H], k0);
        float2 dzt = dotq(&S.ubuf[0], &S.ubuf[VS], wzu2_w, k0);
        if (act) {
            a2w = (((s == 0) ? da2.x : da2.y) + wyu2_b[h]) * wy2[h];
            float zu2 = softplus_f(((s == 0) ? dzt.x : dzt.y) + wzu2_b[0]);
            vw2 = zu2 * fmaxf(wz2[h], 0.f);
            yr = y[(samp + s) * H + h];
            S.yv0[s * VS + h] = a0r;     // y1 = 1
            S.yv1[s * VS + h] = a1r;
        }
    }

    // ---- fixed-point iterations: 4 syncs/iter, lag-4 convergence pipeline ----
    int broke = 0;
    for (int it = 0; it < MAXIT; ++it) {
        __syncthreads();                                   // A: yv*, redW(it-1) ready

        if (tid == 0 && it > 0) {
            float n0 = 0.f, n1 = 0.f;
#pragma unroll
            for (int w = 0; w < 16; w++) { n0 += S.redW[w][0]; n1 += S.redW[w][1]; }
            atomicAdd(&g_res[it - 1], sqrtf(n0) + sqrtf(n1));
            __threadfence();
            atomicAdd(&g_cnt[it - 1], 1);
        }
        if (tid == 3) {
            int f = 0;
            if (it >= LAG) {
                int k = it - LAG;
                while (*((volatile int*)&g_cnt[k]) < NCTA) { }
                __threadfence();
                if (*((volatile float*)&g_res[k]) * (1.f / 256.f) < TOLF) f = 1;
            }
            S.flag = f;
        }

        // M1: s1 = Wy0 @ yv0 (+c0), row access, quarter partial + butterfly
        float m0 = 0.f, m1 = 0.f;
        {
            const float4* W  = (const float4*)&S.Wy0[h * STRIDE + k0];
            const float4* V0 = (const float4*)&S.yv0[k0];
            const float4* V1 = (const float4*)&S.yv0[VS + k0];
#pragma unroll
            for (int c = 0; c < 8; c++) {
                float4 w = W[c], a = V0[c], b = V1[c];
                m0 += w.x * a.x + w.y * a.y + w.z * a.z + w.w * a.w;
                m1 += w.x * b.x + w.y * b.y + w.z * b.z + w.w * b.w;
            }
            m0 += __shfl_xor_sync(0xffffffffu, m0, 1);
            m0 += __shfl_xor_sync(0xffffffffu, m0, 2);
            m1 += __shfl_xor_sync(0xffffffffu, m1, 1);
            m1 += __shfl_xor_sync(0xffffffffu, m1, 2);
        }
        if (act) {
            float s1 = ((s == 0) ? m0 : m1) + c0r;
            float z1, sg1;
            spsig(s1, z1, sg1);
            zs1r = sg1 * zur;
            S.zz[s * VS + h] = z1 * zur;
        }
        __syncthreads();                                   // B

        // M2: s2 = W1p @ zz + Wy1 @ yv1 (+c1), row access
        m0 = 0.f; m1 = 0.f;
        {
            const float4* WA = (const float4*)&S.W1p[h * STRIDE + k0];
            const float4* WB = (const float4*)&S.Wy1[h * STRIDE + k0];
            const float4* Z0 = (const float4*)&S.zz[k0];
            const float4* Z1 = (const float4*)&S.zz[VS + k0];
            const float4* Y0 = (const float4*)&S.yv1[k0];
            const float4* Y1 = (const float4*)&S.yv1[VS + k0];
#pragma unroll
            for (int c = 0; c < 8; c++) {
                float4 A = WA[c], Bm = WB[c];
                float4 z0 = Z0[c], z1v = Z1[c], u0v = Y0[c], u1vv = Y1[c];
                m0 += A.x * z0.x + A.y * z0.y + A.z * z0.z + A.w * z0.w
                    + Bm.x * u0v.x + Bm.y * u0v.y + Bm.z * u0v.z + Bm.w * u0v.w;
                m1 += A.x * z1v.x + A.y * z1v.y + A.z * z1v.z + A.w * z1v.w
                    + Bm.x * u1vv.x + Bm.y * u1vv.y + Bm.z * u1vv.z + Bm.w * u1vv.w;
            }
            m0 += __shfl_xor_sync(0xffffffffu, m0, 1);
            m0 += __shfl_xor_sync(0xffffffffu, m0, 2);
            m1 += __shfl_xor_sync(0xffffffffu, m1, 1);
            m1 += __shfl_xor_sync(0xffffffffu, m1, 2);
        }
        if (act) {
            float s2 = ((s == 0) ? m0 : m1) + c1r;
            float sg2 = 1.f / (1.f + __expf(-s2));
            S.v2[s * VS + h] = vw2 * sg2;
        }
        __syncthreads();                                   // C

        // Phase C: tv = W1p^T @ v2, gA = Wy1^T @ v2 (column access, 2q stagger)
        float t0 = 0.f, t1 = 0.f, g0 = 0.f, g1 = 0.f;
        {
#pragma unroll
            for (int i = 0; i < 32; i++) {
                int kk = k0 + ((i + 2 * q) & 31);
                float va = S.v2[kk], vb = S.v2[VS + kk];
                float wA = S.W1p[kk * STRIDE + h];
                float wB = S.Wy1[kk * STRIDE + h];
                t0 += va * wA;  t1 += vb * wA;
                g0 += va * wB;  g1 += vb * wB;
            }
            t0 += __shfl_xor_sync(0xffffffffu, t0, 1);
            t0 += __shfl_xor_sync(0xffffffffu, t0, 2);
            t1 += __shfl_xor_sync(0xffffffffu, t1, 1);
            t1 += __shfl_xor_sync(0xffffffffu, t1, 2);
            g0 += __shfl_xor_sync(0xffffffffu, g0, 1);
            g0 += __shfl_xor_sync(0xffffffffu, g0, 2);
            g1 += __shfl_xor_sync(0xffffffffu, g1, 1);
            g1 += __shfl_xor_sync(0xffffffffu, g1, 2);
        }
        if (act) {
            float tv = (s == 0) ? t0 : t1;
            gAr      = (s == 0) ? g0 : g1;
            S.v1[s * VS + h] = tv * zs1r;
        }
        __syncthreads();                                   // D

        // Phase D: gB = Wy0^T @ v1 (column access, 2q stagger)
        float b0 = 0.f, b1 = 0.f;
        {
#pragma unroll
            for (int i = 0; i < 32; i++) {
                int kk = k0 + ((i + 2 * q) & 31);
                float va = S.v1[kk], vb = S.v1[VS + kk];
                float w = S.Wy0[kk * STRIDE + h];
                b0 += va * w;  b1 += vb * w;
            }
            b0 += __shfl_xor_sync(0xffffffffu, b0, 1);
            b0 += __shfl_xor_sync(0xffffffffu, b0, 2);
            b1 += __shfl_xor_sync(0xffffffffu, b1, 1);
            b1 += __shfl_xor_sync(0xffffffffu, b1, 2);
        }

        float rres = 0.f, qq = 0.f;
        if (act) {
            float gB = (s == 0) ? b0 : b1;
            float g = a1r * gAr + a0r * gB + a2w + 0.5f * y1r;
            rres = yr - g;
            qq = rres * rres;
        }
        // per-warp residual partials (sum over hg; q lanes stay separate)
        qq += __shfl_xor_sync(0xffffffffu, qq, 4);
        qq += __shfl_xor_sync(0xffffffffu, qq, 8);
        qq += __shfl_xor_sync(0xffffffffu, qq, 16);
        if (lane < 2) S.redW[wrp][lane] = qq;

        if (S.flag) { broke = 1; break; }   // conv at it-LAG -> exact revert below

        if (act) {
            y1r += (4.f / (float)(it + 1)) * rres;
            y1h4 = y1h3; y1h3 = y1h2; y1h2 = y1h1; y1h1 = y1r;
            S.yv0[s * VS + h] = y1r * a0r;
            S.yv1[s * VS + h] = y1r * a1r;
        }
    }
    if (broke && act) y1r = y1h4;   // y1_after(c), c = break_it - LAG

    // ---- output: mean over dims of (y1 + y) per sample ----
    float o = act ? (y1r + yr) : 0.f;
    o += __shfl_xor_sync(0xffffffffu, o, 4);
    o += __shfl_xor_sync(0xffffffffu, o, 8);
    o += __shfl_xor_sync(0xffffffffu, o, 16);
    if (lane < 2) S.redW[wrp][lane] = o;
    __syncthreads();
    if (tid == 0) {
        float o0 = 0.f, o1 = 0.f;
#pragma unroll
        for (int w = 0; w < 16; w++) { o0 += S.redW[w][0]; o1 += S.redW[w][1]; }
        out[samp]     = o0 * (1.f / 128.f);
        out[samp + 1] = o1 * (1.f / 128.f);
    }
}

extern "C" void kernel_launch(void* const* d_in, const int* in_sizes, int n_in,
                              void* d_out, int out_size) {
    (void)in_sizes; (void)n_in; (void)out_size;
    const float* x      = (const float*)d_in[0];
    const float* y      = (const float*)d_in[1];
    const float* wuu0_w = (const float*)d_in[2];
    const float* wuu0_b = (const float*)d_in[3];
    const float* wyu0_w = (const float*)d_in[4];
    const float* wyu0_b = (const float*)d_in[5];
    const float* wy0    = (const float*)d_in[6];
    const float* wu0_w  = (const float*)d_in[7];
    const float* wu0_b  = (const float*)d_in[8];
    const float* wuu1_w = (const float*)d_in[9];
    const float* wuu1_b = (const float*)d_in[10];
    const float* wzu1_w = (const float*)d_in[11];
    const float* wzu1_b = (const float*)d_in[12];
    const float* wz1    = (const float*)d_in[13];
    const float* wyu1_w = (const float*)d_in[14];
    const float* wyu1_b = (const float*)d_in[15];
    const float* wy1    = (const float*)d_in[16];
    const float* wu1_w  = (const float*)d_in[17];
    const float* wu1_b  = (const float*)d_in[18];
    const float* wzu2_w = (const float*)d_in[19];
    const float* wzu2_b = (const float*)d_in[20];
    const float* wz2    = (const float*)d_in[21];
    const float* wyu2_w = (const float*)d_in[22];
    const float* wyu2_b = (const float*)d_in[23];
    const float* wy2    = (const float*)d_in[24];
    // d_in[25] (wu2_w), d_in[26] (wu2_b) do not affect the gradient / output.

    size_t smem = sizeof(Smem);
    cudaFuncSetAttribute(pblnn_kernel, cudaFuncAttributeMaxDynamicSharedMemorySize, (int)smem);

    pblnn_init_kernel<<<2, 256>>>();
    pblnn_kernel<<<NCTA, NTHREADS, smem>>>(
        x, y,
        wuu0_w, wuu0_b, wyu0_w, wyu0_b, wy0, wu0_w, wu0_b,
        wuu1_w, wuu1_b, wzu1_w, wzu1_b, wz1, wyu1_w, wyu1_b, wy1, wu1_w, wu1_b,
        wzu2_w, wzu2_b, wz2, wyu2_w, wyu2_b, wy2,
        (float*)d_out);
}

// round 5
// speedup vs baseline: 1.9297x; 1.9297x over previous
#include <cuda_runtime.h>
#include <math.h>

#define H        128
#define STRIDE   132      // 132 % 32 == 4 -> conflict-free row AND column smem access
#define NCTA     128
#define NTHREADS 512
#define MAXIT    500
#define TOLF     1e-3f

__device__ float g_res[MAXIT];   // per-iteration residual accumulators
__device__ int   g_cnt[MAXIT];   // per-iteration post counters (skew-safe)

struct __align__(16) Smem {
    float Wy0[H * STRIDE];
    float Wy1[H * STRIDE];
    float W1p[H * STRIDE];
    float yv0[2][H];
    float yv1[2][H];
    float zz [2][H];
    float v2 [2][H];
    float v1 [2][H];
    float P1[4][2][STRIDE];   // [quarter][sample][h], padded inner
    float P2[4][2][STRIDE];
    float xbuf[2][H];
    float ubuf[2][H];
    float red[8];
    int   flag;
};

__global__ void pblnn_init_kernel() {
    int t = blockIdx.x * blockDim.x + threadIdx.x;
    if (t < MAXIT) { g_res[t] = 0.f; g_cnt[t] = 0; }
}

__device__ __forceinline__ float softplus_f(float s) {
    float e = __expf(s);
    float z = __logf(1.f + e);
    return (s > 15.f) ? s : z;
}

__device__ __forceinline__ void spsig(float s, float& z, float& sg) {
    float e = __expf(s);
    float zz_ = __logf(1.f + e);
    float sgg = e / (1.f + e);
    if (s > 15.f) { zz_ = s; sgg = 1.f; }
    z = zz_; sg = sgg;
}

// single-sample dot: smem vector (128) . gmem row (128), float4 loads (one-time)
__device__ __forceinline__ float dot1(const float* xs, const float* __restrict__ w) {
    float a = 0.f, b = 0.f;
#pragma unroll
    for (int j = 0; j < H; j += 8) {
        float4 wv0 = __ldg((const float4*)&w[j]);
        float4 wv1 = __ldg((const float4*)&w[j + 4]);
        float4 u0 = *(const float4*)&xs[j];
        float4 u1 = *(const float4*)&xs[j + 4];
        a += wv0.x * u0.x + wv0.y * u0.y + wv0.z * u0.z + wv0.w * u0.w;
        b += wv1.x * u1.x + wv1.y * u1.y + wv1.z * u1.z + wv1.w * u1.w;
    }
    return a + b;
}

__global__ __launch_bounds__(NTHREADS, 1)
void pblnn_kernel(
    const float* __restrict__ x,      const float* __restrict__ y,
    const float* __restrict__ wuu0_w, const float* __restrict__ wuu0_b,
    const float* __restrict__ wyu0_w, const float* __restrict__ wyu0_b,
    const float* __restrict__ wy0,
    const float* __restrict__ wu0_w,  const float* __restrict__ wu0_b,
    const float* __restrict__ wuu1_w, const float* __restrict__ wuu1_b,
    const float* __restrict__ wzu1_w, const float* __restrict__ wzu1_b,
    const float* __restrict__ wz1,
    const float* __restrict__ wyu1_w, const float* __restrict__ wyu1_b,
    const float* __restrict__ wy1,
    const float* __restrict__ wu1_w,  const float* __restrict__ wu1_b,
    const float* __restrict__ wzu2_w, const float* __restrict__ wzu2_b,
    const float* __restrict__ wz2,
    const float* __restrict__ wyu2_w, const float* __restrict__ wyu2_b,
    const float* __restrict__ wy2,
    float* __restrict__ out)
{
    extern __shared__ char smem_raw[];
    Smem& S = *reinterpret_cast<Smem*>(smem_raw);

    const int tid  = threadIdx.x;
    const int h    = tid & (H - 1);
    const int q    = tid >> 7;          // quarter 0..3
    const int k0   = q * 32;
    const bool act = (q < 2);           // elementwise lanes; s = q
    const int s    = q & 1;
    const int samp = blockIdx.x * 2;

    // ---- stage x + weights into smem (float4, stride-132 padded) ----
    for (int e = tid; e < 2 * H; e += NTHREADS)
        S.xbuf[e >> 7][e & 127] = x[samp * H + e];
    for (int e = tid; e < H * H / 4; e += NTHREADS) {
        int r = e >> 5, c4 = (e & 31) * 4;
        *(float4*)&S.Wy0[r * STRIDE + c4] = __ldg((const float4*)&wy0[r * H + c4]);
        *(float4*)&S.Wy1[r * STRIDE + c4] = __ldg((const float4*)&wy1[r * H + c4]);
        float4 wv = __ldg((const float4*)&wz1[r * H + c4]);
        wv.x = fmaxf(wv.x, 0.f); wv.y = fmaxf(wv.y, 0.f);
        wv.z = fmaxf(wv.z, 0.f); wv.w = fmaxf(wv.w, 0.f);
        *(float4*)&S.W1p[r * STRIDE + c4] = wv;
    }
    __syncthreads();

    // ---- y-independent precompute (one-time; act threads, one sample each) ----
    float a0r = 0.f, a1r = 0.f, c0r = 0.f, c1r = 0.f, zur = 0.f;
    float vw2 = 0.f, a2w = 0.f, yr = 0.f;
    float y1r = 1.f, yhist = 1.f;       // yhist = y1_after(it-2) at loop bottom of it
    float zs1r = 0.f, gAr = 0.f;

    if (act) {
        const float* xs = S.xbuf[s];
        float u0 = softplus_f(dot1(xs, &wuu0_w[h * H]) + wuu0_b[h]);
        a0r = dot1(xs, &wyu0_w[h * H]) + wyu0_b[h];
        c0r = dot1(xs, &wu0_w[h * H]) + wu0_b[h];
        S.ubuf[s][h] = u0;
    }
    __syncthreads();
    float u1 = 0.f;
    if (act) {
        const float* us = S.ubuf[s];
        u1  = softplus_f(dot1(us, &wuu1_w[h * H]) + wuu1_b[h]);
        zur = softplus_f(dot1(us, &wzu1_w[h * H]) + wzu1_b[h]);
        a1r = dot1(us, &wyu1_w[h * H]) + wyu1_b[h];
        c1r = dot1(us, &wu1_w[h * H]) + wu1_b[h];
    }
    __syncthreads();
    if (act) S.ubuf[s][h] = u1;
    __syncthreads();
    if (act) {
        const float* us = S.ubuf[s];
        a2w = (dot1(us, &wyu2_w[h * H]) + wyu2_b[h]) * wy2[h];
        float zu2 = softplus_f(dot1(us, wzu2_w) + wzu2_b[0]);
        vw2 = zu2 * fmaxf(wz2[h], 0.f);
        yr = y[(samp + s) * H + h];
        S.yv0[s][h] = a0r;      // y1 = 1
        S.yv1[s][h] = a1r;
    }
    __syncthreads();            // yv ready for iter 0

    // ---- fixed-point iterations: 8 syncs/iter, lag-2 convergence pipeline ----
    int broke = 0;
    for (int it = 0; it < MAXIT; ++it) {
        // post residual of it-1 (redW synced at loop-end barrier)
        if (tid == 0 && it > 0) {
            float n0 = sqrtf(S.red[0] + S.red[1] + S.red[2] + S.red[3]);
            float n1 = sqrtf(S.red[4] + S.red[5] + S.red[6] + S.red[7]);
            atomicAdd(&g_res[it - 1], n0 + n1);
            __threadfence();
            atomicAdd(&g_cnt[it - 1], 1);
        }
        // checker: ~2 iterations of slack before flag is consumed
        if (tid == 384) {
            int f = 0;
            if (it >= 2) {
                int k = it - 2;
                while (*((volatile int*)&g_cnt[k]) < NCTA) { }
                __threadfence();
                if (*((volatile float*)&g_res[k]) * (1.f / 256.f) < TOLF) f = 1;
            }
            S.flag = f;
        }

        // M1: s1 partial over j in [k0,k0+32), weights row-wise from smem
        {
            const float4* W  = (const float4*)&S.Wy0[h * STRIDE + k0];
            const float4* V0 = (const float4*)&S.yv0[0][k0];
            const float4* V1 = (const float4*)&S.yv0[1][k0];
            float m0a = 0.f, m0b = 0.f, m1a = 0.f, m1b = 0.f;
#pragma unroll
            for (int c = 0; c < 8; c += 2) {
                float4 w = W[c], a = V0[c], b = V1[c];
                m0a += w.x * a.x + w.y * a.y + w.z * a.z + w.w * a.w;
                m1a += w.x * b.x + w.y * b.y + w.z * b.z + w.w * b.w;
                float4 w2 = W[c + 1], a2 = V0[c + 1], b2 = V1[c + 1];
                m0b += w2.x * a2.x + w2.y * a2.y + w2.z * a2.z + w2.w * a2.w;
                m1b += w2.x * b2.x + w2.y * b2.y + w2.z * b2.z + w2.w * b2.w;
            }
            S.P1[q][0][h] = m0a + m0b;  S.P1[q][1][h] = m1a + m1b;
        }
        __syncthreads();                                   // #2

        if (act) {
            float s1 = S.P1[0][s][h] + S.P1[1][s][h] + S.P1[2][s][h] + S.P1[3][s][h] + c0r;
            float z1, sg1;
            spsig(s1, z1, sg1);
            zs1r = sg1 * zur;
            S.zz[s][h] = z1 * zur;
        }
        __syncthreads();                                   // #3

        // M2: s2 partial = W1p@zz + Wy1@yv1, weights row-wise from smem
        {
            const float4* WA = (const float4*)&S.W1p[h * STRIDE + k0];
            const float4* WB = (const float4*)&S.Wy1[h * STRIDE + k0];
            const float4* Z0 = (const float4*)&S.zz[0][k0];
            const float4* Z1 = (const float4*)&S.zz[1][k0];
            const float4* Y0 = (const float4*)&S.yv1[0][k0];
            const float4* Y1 = (const float4*)&S.yv1[1][k0];
            float mA0 = 0.f, mA1 = 0.f, mB0 = 0.f, mB1 = 0.f;
#pragma unroll
            for (int c = 0; c < 8; c++) {
                float4 A = WA[c], Bm = WB[c];
                float4 z0 = Z0[c], z1v = Z1[c], u0v = Y0[c], u1v = Y1[c];
                mA0 += A.x * z0.x + A.y * z0.y + A.z * z0.z + A.w * z0.w;
                mB0 += Bm.x * u0v.x + Bm.y * u0v.y + Bm.z * u0v.z + Bm.w * u0v.w;
                mA1 += A.x * z1v.x + A.y * z1v.y + A.z * z1v.z + A.w * z1v.w;
                mB1 += Bm.x * u1v.x + Bm.y * u1v.y + Bm.z * u1v.z + Bm.w * u1v.w;
            }
            S.P1[q][0][h] = mA0 + mB0;  S.P1[q][1][h] = mA1 + mB1;
        }
        __syncthreads();                                   // #4

        if (act) {
            float s2 = S.P1[0][s][h] + S.P1[1][s][h] + S.P1[2][s][h] + S.P1[3][s][h] + c1r;
            float sg2 = 1.f / (1.f + __expf(-s2));
            S.v2[s][h] = vw2 * sg2;
        }
        __syncthreads();                                   // #5

        // C: tv partial (W1p cols) + gA partial (Wy1 cols) fused
        {
            float tA0 = 0.f, tA1 = 0.f, gA0 = 0.f, gA1 = 0.f;
#pragma unroll
            for (int c = 0; c < 8; c++) {
                int kp = k0 + 4 * c;
                float4 a = *(const float4*)&S.v2[0][kp];
                float4 b = *(const float4*)&S.v2[1][kp];
#define STC(r, av, bv) { \
                float wA = S.W1p[(kp + r) * STRIDE + h]; \
                float wB = S.Wy1[(kp + r) * STRIDE + h]; \
                tA0 += (av) * wA;  tA1 += (bv) * wA; \
                gA0 += (av) * wB;  gA1 += (bv) * wB; }
                STC(0, a.x, b.x) STC(1, a.y, b.y) STC(2, a.z, b.z) STC(3, a.w, b.w)
#undef STC
            }
            S.P1[q][0][h] = tA0;  S.P1[q][1][h] = tA1;
            S.P2[q][0][h] = gA0;  S.P2[q][1][h] = gA1;
        }
        __syncthreads();                                   // #6

        if (act) {
            float tv = S.P1[0][s][h] + S.P1[1][s][h] + S.P1[2][s][h] + S.P1[3][s][h];
            gAr      = S.P2[0][s][h] + S.P2[1][s][h] + S.P2[2][s][h] + S.P2[3][s][h];
            S.v1[s][h] = tv * zs1r;
        }
        __syncthreads();                                   // #7

        // D: gB partial (Wy0 cols)
        {
            float g0 = 0.f, g1 = 0.f;
#pragma unroll
            for (int c = 0; c < 8; c++) {
                int kp = k0 + 4 * c;
                float4 a = *(const float4*)&S.v1[0][kp];
                float4 b = *(const float4*)&S.v1[1][kp];
#define STD(r, av, bv) { \
                float w = S.Wy0[(kp + r) * STRIDE + h]; \
                g0 += (av) * w;  g1 += (bv) * w; }
                STD(0, a.x, b.x) STD(1, a.y, b.y) STD(2, a.z, b.z) STD(3, a.w, b.w)
#undef STD
            }
            S.P1[q][0][h] = g0;  S.P1[q][1][h] = g1;
        }
        __syncthreads();                                   // #8

        float rres = 0.f;
        if (act) {
            float gB = S.P1[0][s][h] + S.P1[1][s][h] + S.P1[2][s][h] + S.P1[3][s][h];
            float g = a1r * gAr + a0r * gB + a2w + 0.5f * y1r;
            rres = yr - g;
            float qq = rres * rres;
#pragma unroll
            for (int o = 16; o; o >>= 1)
                qq += __shfl_xor_sync(0xffffffffu, qq, o);
            if ((h & 31) == 0) S.red[tid >> 5] = qq;   // warps 0..7
        }

        // flag = conv(it-2); break BEFORE this iteration's update.
        // y1 currently = y1_after(it-1); required = y1_after(it-2) = yhist.
        if (S.flag) { broke = 1; break; }

        if (act) {
            yhist = y1r;                       // y1_after(it-1) for next iteration's revert
            y1r += (4.f / (float)(it + 1)) * rres;
            S.yv0[s][h] = y1r * a0r;
            S.yv1[s][h] = y1r * a1r;
        }
        __syncthreads();     // #E: redW ready for tid0-post, yv ready for next M1,
                             //     and flag not yet overwritten by next checker write
    }
    if (broke && act) y1r = yhist;   // exact revert to y1_after(break_it - 2)

    // ---- output: mean over dims of (y1 + y) per sample ----
    float o = act ? (y1r + yr) : 0.f;
    if (act) {
#pragma unroll
        for (int off = 16; off; off >>= 1)
            o += __shfl_xor_sync(0xffffffffu, o, off);
        if ((h & 31) == 0) S.red[tid >> 5] = o;
    }
    __syncthreads();
    if (tid == 0) {
        out[samp]     = (S.red[0] + S.red[1] + S.red[2] + S.red[3]) * (1.f / 128.f);
        out[samp + 1] = (S.red[4] + S.red[5] + S.red[6] + S.red[7]) * (1.f / 128.f);
    }
}

extern "C" void kernel_launch(void* const* d_in, const int* in_sizes, int n_in,
                              void* d_out, int out_size) {
    (void)in_sizes; (void)n_in; (void)out_size;
    const float* x      = (const float*)d_in[0];
    const float* y      = (const float*)d_in[1];
    const float* wuu0_w = (const float*)d_in[2];
    const float* wuu0_b = (const float*)d_in[3];
    const float* wyu0_w = (const float*)d_in[4];
    const float* wyu0_b = (const float*)d_in[5];
    const float* wy0    = (const float*)d_in[6];
    const float* wu0_w  = (const float*)d_in[7];
    const float* wu0_b  = (const float*)d_in[8];
    const float* wuu1_w = (const float*)d_in[9];
    const float* wuu1_b = (const float*)d_in[10];
    const float* wzu1_w = (const float*)d_in[11];
    const float* wzu1_b = (const float*)d_in[12];
    const float* wz1    = (const float*)d_in[13];
    const float* wyu1_w = (const float*)d_in[14];
    const float* wyu1_b = (const float*)d_in[15];
    const float* wy1    = (const float*)d_in[16];
    const float* wu1_w  = (const float*)d_in[17];
    const float* wu1_b  = (const float*)d_in[18];
    const float* wzu2_w = (const float*)d_in[19];
    const float* wzu2_b = (const float*)d_in[20];
    const float* wz2    = (const float*)d_in[21];
    const float* wyu2_w = (const float*)d_in[22];
    const float* wyu2_b = (const float*)d_in[23];
    const float* wy2    = (const float*)d_in[24];
    // d_in[25] (wu2_w), d_in[26] (wu2_b) do not affect the gradient / output.

    size_t smem = sizeof(Smem);
    cudaFuncSetAttribute(pblnn_kernel, cudaFuncAttributeMaxDynamicSharedMemorySize, (int)smem);

    pblnn_init_kernel<<<2, 256>>>();
    pblnn_kernel<<<NCTA, NTHREADS, smem>>>(
        x, y,
        wuu0_w, wuu0_b, wyu0_w, wyu0_b, wy0, wu0_w, wu0_b,
        wuu1_w, wuu1_b, wzu1_w, wzu1_b, wz1, wyu1_w, wyu1_b, wy1, wu1_w, wu1_b,
        wzu2_w, wzu2_b, wz2, wyu2_w, wyu2_b, wy2,
        (float*)d_out);
}